// round 14
// baseline (speedup 1.0000x reference)
#include <cuda_runtime.h>
#include <cuda_fp16.h>
#include <math.h>
#include <stdint.h>

#define N_ELEC 64
#define N_NUC  16
#define N_PART 80
#define BASIS  32
#define KDIM   128
#define DDIM   128
#define BSZ    256
#define LAYERS 3
#define NBI    (BSZ * N_ELEC)

#define TILES_PER_CTA 8
#define CFC_GRID (NBI / TILES_PER_CTA)   // 2048

// cfconv SMEM word-layout (4-byte words): d x2, h x2, zs
#define DPADW 20
#define HPADW 68
#define ZPAD  132
#define OFF_D0 0
#define OFF_D1 (N_PART * DPADW)              // 1600
#define OFF_H0 (2 * N_PART * DPADW)          // 3200
#define OFF_H1 (OFF_H0 + N_PART * HPADW)     // 8640
#define OFF_ZS (OFF_H1 + N_PART * HPADW)     // 14080
#define SMEM_WORDS (OFF_ZS + N_PART * ZPAD)  // 24640 words = 98560 B

// side-kernel SMEM row stride (words)
#define ASTR 68

// Scratch (no cudaMalloc allowed)
__device__ float g_zs[BSZ * N_PART * KDIM];      // (b, j, k)
__device__ float g_zsout[BSZ * N_ELEC * KDIM];   // cfconv output
__device__ float g_zrow[2 * KDIM];               // layer-0 zs rows (up, dn)

__device__ __forceinline__ float ssp_f(float x) {
    float ax = fabsf(x);
    return fmaxf(x, 0.0f) + __logf(1.0f + __expf(-ax)) - 0.69314718055994530942f;
}

__device__ __forceinline__ uint32_t pack_h2(float lo, float hi) {
    __half2 h = __floats2half2_rn(lo, hi);
    return *(uint32_t*)&h;
}

__device__ __forceinline__ uint32_t smem_u32(const void* p) {
    uint32_t a;
    asm("{ .reg .u64 t; cvta.to.shared.u64 t, %1; cvt.u32.u64 %0, t; }" : "=r"(a) : "l"(p));
    return a;
}

// m16n8k16 fp16 mma, fp32 accumulate (baseline PTX, sm_80+)
__device__ __forceinline__ void mma_f16(float* d, const uint32_t* a,
                                        uint32_t b0, uint32_t b1) {
    asm volatile(
        "mma.sync.aligned.m16n8k16.row.col.f32.f16.f16.f32 "
        "{%0,%1,%2,%3}, {%4,%5,%6,%7}, {%8,%9}, {%0,%1,%2,%3};"
        : "+f"(d[0]), "+f"(d[1]), "+f"(d[2]), "+f"(d[3])
        : "r"(a[0]), "r"(a[1]), "r"(a[2]), "r"(a[3]), "r"(b0), "r"(b1));
}

// ldmatrix x4 (sm_75+ baseline PTX)
#define LDSM4(r0, r1, r2, r3, addr) \
    asm volatile("ldmatrix.sync.aligned.m8n8.x4.shared.b16 {%0,%1,%2,%3}, [%4];" \
                 : "=r"(r0), "=r"(r1), "=r"(r2), "=r"(r3) : "r"(addr))

// ---------------------------------------------------------------------------
// Layer-0 zs: xs rows are e_up / e_dn -> only 2 distinct zs rows. 1 block.
// ---------------------------------------------------------------------------
__global__ void z0_kernel(const float* __restrict__ emb_e,
                          const float* __restrict__ eiW) {
    __shared__ float eup[DDIM], edn[DDIM];
    int k = threadIdx.x;   // 128 threads
    eup[k] = emb_e[k];
    edn[k] = emb_e[N_ELEC / 2 * DDIM + k];
    __syncthreads();
    float au = 0.f, ad = 0.f;
#pragma unroll 4
    for (int d = 0; d < DDIM; ++d) {
        float w = eiW[d * KDIM + k];
        au = fmaf(eup[d], w, au);
        ad = fmaf(edn[d], w, ad);
    }
    g_zrow[k] = au;
    g_zrow[KDIM + k] = ad;
}

// ---------------------------------------------------------------------------
// Broadcast fill: xs <- emb_e; g_zs elec <- g_zrow; g_zs nuc <- emb_n
// ---------------------------------------------------------------------------
__global__ void fill0_kernel(const float* __restrict__ emb_e,
                             const float* __restrict__ emb_n,
                             float* __restrict__ xs) {
    int idx = blockIdx.x * blockDim.x + threadIdx.x;
    if (idx < BSZ * N_PART * KDIM) {
        int jk = idx % (N_PART * KDIM);
        int j = jk >> 7, k = jk & 127;
        float v;
        if (j < N_ELEC) v = g_zrow[(j >= N_ELEC / 2 ? KDIM : 0) + k];
        else            v = emb_n[(j - N_ELEC) * KDIM + k];
        g_zs[idx] = v;
    }
    if (idx < BSZ * N_ELEC * DDIM) {
        xs[idx] = emb_e[idx % (N_ELEC * DDIM)];
    }
}

// ---------------------------------------------------------------------------
// Fused output MLP + next-layer zs (unchanged from R13)
// ---------------------------------------------------------------------------
extern __shared__ uint32_t dyn_smem_w[];

__global__ void __launch_bounds__(256) outzs_mma_kernel(
    const float* __restrict__ eoW1, const float* __restrict__ eob1,
    const float* __restrict__ eoW2, const float* __restrict__ eob2,
    const float* __restrict__ eiW_next,   // may be nullptr (last layer)
    float* __restrict__ xs)
{
    uint32_t* w1_w = dyn_smem_w;
    uint32_t* w2_w = dyn_smem_w + 128 * ASTR;
    uint32_t* a_w  = dyn_smem_w + 2 * 128 * ASTR;
    uint32_t* ei_w = dyn_smem_w + 3 * 128 * ASTR;
    float*    bias = (float*)(dyn_smem_w + 4 * 128 * ASTR);

    const int tid  = threadIdx.x;
    const int wid  = tid >> 5;
    const int lane = tid & 31;
    const int g    = lane >> 2;
    const int tg   = lane & 3;
    const int rblk = blockIdx.x * 128;
    const int r0   = wid * 16 + g;

    for (int idx = tid; idx < 128 * 64; idx += 256) {
        int kp = idx >> 7, d = idx & 127;
        w1_w[d * ASTR + kp] = pack_h2(eoW1[(2 * kp) * DDIM + d],
                                      eoW1[(2 * kp + 1) * DDIM + d]);
        w2_w[d * ASTR + kp] = pack_h2(eoW2[(2 * kp) * DDIM + d],
                                      eoW2[(2 * kp + 1) * DDIM + d]);
        if (eiW_next)
            ei_w[d * ASTR + kp] = pack_h2(eiW_next[(2 * kp) * KDIM + d],
                                          eiW_next[(2 * kp + 1) * KDIM + d]);
    }
    for (int idx = tid; idx < 128 * 64; idx += 256) {
        int r = idx >> 6, kw = idx & 63;
        float2 v = *(const float2*)&g_zsout[(size_t)(rblk + r) * KDIM + kw * 2];
        a_w[r * ASTR + kw] = pack_h2(v.x, v.y);
    }
    if (tid < 128) { bias[tid] = eob1[tid]; bias[128 + tid] = eob2[tid]; }
    __syncthreads();

    float acc[16][4];
#pragma unroll
    for (int nt = 0; nt < 16; ++nt) {
        acc[nt][0] = 0.f; acc[nt][1] = 0.f; acc[nt][2] = 0.f; acc[nt][3] = 0.f;
    }
#pragma unroll
    for (int kk = 0; kk < 8; ++kk) {
        uint32_t a[4];
        int ab = r0 * ASTR + kk * 8 + tg;
        a[0] = a_w[ab];
        a[1] = a_w[ab + 8 * ASTR];
        a[2] = a_w[ab + 4];
        a[3] = a_w[ab + 8 * ASTR + 4];
#pragma unroll
        for (int nt = 0; nt < 16; ++nt) {
            int nb = (nt * 8 + g) * ASTR + kk * 8 + tg;
            mma_f16(acc[nt], a, w1_w[nb], w1_w[nb + 4]);
        }
    }
    __syncthreads();

#pragma unroll
    for (int nt = 0; nt < 16; ++nt) {
        int d0 = nt * 8 + 2 * tg;
        float ba = bias[d0], bb = bias[d0 + 1];
        w1_w[r0 * ASTR + nt * 4 + tg] =
            pack_h2(ssp_f(acc[nt][0] + ba), ssp_f(acc[nt][1] + bb));
        w1_w[(r0 + 8) * ASTR + nt * 4 + tg] =
            pack_h2(ssp_f(acc[nt][2] + ba), ssp_f(acc[nt][3] + bb));
        acc[nt][0] = 0.f; acc[nt][1] = 0.f; acc[nt][2] = 0.f; acc[nt][3] = 0.f;
    }
    __syncthreads();

#pragma unroll
    for (int kk = 0; kk < 8; ++kk) {
        uint32_t a[4];
        int ab = r0 * ASTR + kk * 8 + tg;
        a[0] = w1_w[ab];
        a[1] = w1_w[ab + 8 * ASTR];
        a[2] = w1_w[ab + 4];
        a[3] = w1_w[ab + 8 * ASTR + 4];
#pragma unroll
        for (int nt = 0; nt < 16; ++nt) {
            int nb = (nt * 8 + g) * ASTR + kk * 8 + tg;
            mma_f16(acc[nt], a, w2_w[nb], w2_w[nb + 4]);
        }
    }

    float* x0 = xs + (size_t)(rblk + r0) * DDIM;
    float* x1 = xs + (size_t)(rblk + r0 + 8) * DDIM;
#pragma unroll
    for (int nt = 0; nt < 16; ++nt) {
        int d0 = nt * 8 + 2 * tg;
        float ba = bias[128 + d0], bb = bias[128 + d0 + 1];
        float2 v0 = *(float2*)&x0[d0];
        float2 v1 = *(float2*)&x1[d0];
        v0.x += acc[nt][0] + ba;  v0.y += acc[nt][1] + bb;
        v1.x += acc[nt][2] + ba;  v1.y += acc[nt][3] + bb;
        *(float2*)&x0[d0] = v0;
        *(float2*)&x1[d0] = v1;
        if (eiW_next) {
            a_w[r0 * ASTR + nt * 4 + tg]       = pack_h2(v0.x, v0.y);
            a_w[(r0 + 8) * ASTR + nt * 4 + tg] = pack_h2(v1.x, v1.y);
        }
    }

    if (!eiW_next) return;
    __syncthreads();

#pragma unroll
    for (int nt = 0; nt < 16; ++nt) {
        acc[nt][0] = 0.f; acc[nt][1] = 0.f; acc[nt][2] = 0.f; acc[nt][3] = 0.f;
    }
#pragma unroll
    for (int kk = 0; kk < 8; ++kk) {
        uint32_t a[4];
        int ab = r0 * ASTR + kk * 8 + tg;
        a[0] = a_w[ab];
        a[1] = a_w[ab + 8 * ASTR];
        a[2] = a_w[ab + 4];
        a[3] = a_w[ab + 8 * ASTR + 4];
#pragma unroll
        for (int nt = 0; nt < 16; ++nt) {
            int nb = (nt * 8 + g) * ASTR + kk * 8 + tg;
            mma_f16(acc[nt], a, ei_w[nb], ei_w[nb + 4]);
        }
    }
    const int row0 = rblk + r0;
    const int b0 = row0 >> 6, j0r = row0 & 63;
    const int row1 = row0 + 8;
    const int b1 = row1 >> 6, j1r = row1 & 63;
    float* z0p = g_zs + ((size_t)b0 * N_PART + j0r) * KDIM;
    float* z1p = g_zs + ((size_t)b1 * N_PART + j1r) * KDIM;
#pragma unroll
    for (int nt = 0; nt < 16; ++nt) {
        int k0 = nt * 8 + 2 * tg;
        *(float2*)&z0p[k0] = make_float2(acc[nt][0], acc[nt][1]);
        *(float2*)&z1p[k0] = make_float2(acc[nt][2], acc[nt][3]);
    }
}

// ---------------------------------------------------------------------------
// cfconv: pair-tiled. Two tiles per phase-pair share all A operands;
// 1 barrier per tile (2 per pair); next-pair d fills issued after sync#1,
// consumed after sync#2 (latency hidden behind 160 mma).
// ---------------------------------------------------------------------------
__global__ void __launch_bounds__(256, 2) cfconv_mma_kernel(
    const float* __restrict__ dists,
    const float* __restrict__ kW1, const float* __restrict__ kb1,
    const float* __restrict__ kW2, const float* __restrict__ kb2)
{
    uint32_t* d_sw0 = dyn_smem_w + OFF_D0;
    uint32_t* d_sw1 = dyn_smem_w + OFF_D1;
    __half*   h_sh0 = (__half*)(dyn_smem_w + OFF_H0);
    __half*   h_sh1 = (__half*)(dyn_smem_w + OFF_H1);
    float*    zs_s  = (float*)(dyn_smem_w + OFF_ZS);

    const int tid  = threadIdx.x;
    const int wid  = tid >> 5;
    const int lane = tid & 31;
    const int g    = lane >> 2;
    const int tg   = lane & 3;
    const int m0   = wid * 16 + g;
    const int m1   = m0 + 8;

    const int role = lane >> 3;
    const int rrow = lane & 7;
    const uint32_t doff = rrow * (DPADW * 4) + (role >> 1) * 32 + (role & 1) * 16;
    const uint32_t hoff = rrow * (HPADW * 4) + (role >> 1) * 32 + (role & 1) * 16;
    const uint32_t ldsm_d[2] = { smem_u32(d_sw0) + doff, smem_u32(d_sw1) + doff };
    const uint32_t ldsm_h[2] = { smem_u32(h_sh0) + hoff, smem_u32(h_sh1) + hoff };

    uint32_t a1r[2][4];
#pragma unroll
    for (int kk = 0; kk < 2; ++kk) {
        int f = kk * 16 + 2 * tg;
        a1r[kk][0] = pack_h2(kW1[f * KDIM + m0],       kW1[(f + 1) * KDIM + m0]);
        a1r[kk][1] = pack_h2(kW1[f * KDIM + m1],       kW1[(f + 1) * KDIM + m1]);
        a1r[kk][2] = pack_h2(kW1[(f + 8) * KDIM + m0], kW1[(f + 9) * KDIM + m0]);
        a1r[kk][3] = pack_h2(kW1[(f + 8) * KDIM + m1], kW1[(f + 9) * KDIM + m1]);
    }
    uint32_t a2r[8][4];
#pragma unroll
    for (int kk = 0; kk < 8; ++kk) {
        int mm = kk * 16 + 2 * tg;
        a2r[kk][0] = pack_h2(kW2[mm * KDIM + m0],       kW2[(mm + 1) * KDIM + m0]);
        a2r[kk][1] = pack_h2(kW2[mm * KDIM + m1],       kW2[(mm + 1) * KDIM + m1]);
        a2r[kk][2] = pack_h2(kW2[(mm + 8) * KDIM + m0], kW2[(mm + 9) * KDIM + m0]);
        a2r[kk][3] = pack_h2(kW2[(mm + 8) * KDIM + m1], kW2[(mm + 9) * KDIM + m1]);
    }
    const __half2 kb1a2 = __half2half2(__float2half_rn(kb1[m0]));
    const __half2 kb1b2 = __half2half2(__float2half_rn(kb1[m1]));
    const float kb2a = kb2[m0], kb2b = kb2[m1];

    const __half2 D1 = __float2half2_rn( 0.5f);
    const __half2 D2 = __float2half2_rn(-8.3333333e-2f);
    const __half2 D3 = __float2half2_rn( 2.2222222e-2f);
    const __half2 D4 = __float2half2_rn(-6.7460317e-3f);
    const __half2 D5 = __float2half2_rn( 2.1869489e-3f);
    const __half2 HHALF = __float2half2_rn(0.5f);

    const int bi0 = blockIdx.x * TILES_PER_CTA;
    const int b   = bi0 >> 6;      // 8 | 64 -> constant per CTA

    // prologue: stage zs + fill both d buffers for pair 0
    {
#pragma unroll
        for (int sub = 0; sub < 2; ++sub) {
            uint32_t* dd = sub ? d_sw1 : d_sw0;
            const float* dptr = dists + (size_t)(bi0 + sub) * (N_PART * BASIS);
            for (int idx = tid; idx < N_PART * (BASIS / 2); idx += 256) {
                int j = idx >> 4, q = idx & 15;
                float2 v = *(const float2*)(dptr + j * BASIS + q * 2);
                dd[j * DPADW + q] = pack_h2(v.x, v.y);
            }
        }
        const float* zsb = g_zs + (size_t)b * (N_PART * KDIM);
        for (int idx = tid; idx < (N_PART * KDIM) / 4; idx += 256) {
            int j = idx >> 5, q = idx & 31;
            float4 v = *(const float4*)(zsb + j * KDIM + q * 4);
            *(float4*)&zs_s[j * ZPAD + q * 4] = v;
        }
    }
    __syncthreads();

#pragma unroll 1
    for (int p = 0; p < TILES_PER_CTA / 2; ++p) {
        const int biA = bi0 + 2 * p;

        // ---- GEMM1 + epi1 for both sub-tiles ----
#pragma unroll
        for (int sub = 0; sub < 2; ++sub) {
            const uint32_t ld = ldsm_d[sub];
            __half* hh = sub ? h_sh1 : h_sh0;
            float acc[10][4];
#pragma unroll
            for (int nt = 0; nt < 10; ++nt) {
                acc[nt][0] = 0.f; acc[nt][1] = 0.f;
                acc[nt][2] = 0.f; acc[nt][3] = 0.f;
            }
#pragma unroll
            for (int nt = 0; nt < 10; ++nt) {
                uint32_t r0, r1, r2, r3;
                LDSM4(r0, r1, r2, r3, ld + nt * (8 * DPADW * 4));
                mma_f16(acc[nt], a1r[0], r0, r1);
                mma_f16(acc[nt], a1r[1], r2, r3);
            }
#pragma unroll
            for (int nt = 0; nt < 10; ++nt) {
                const int j0 = nt * 8 + 2 * tg;
                const int j1 = j0 + 1;
                __half2 x01 = __hadd2(__floats2half2_rn(acc[nt][0], acc[nt][1]), kb1a2);
                __half2 x23 = __hadd2(__floats2half2_rn(acc[nt][2], acc[nt][3]), kb1b2);
                __half2 y01 = __hmul2(x01, HHALF);
                __half2 y23 = __hmul2(x23, HHALF);
                __half2 v01 = __hmul2(y01, y01);
                __half2 v23 = __hmul2(y23, y23);
                __half2 p01 = __hfma2(v01, D5, D4);
                __half2 p23 = __hfma2(v23, D5, D4);
                p01 = __hfma2(v01, p01, D3);  p23 = __hfma2(v23, p23, D3);
                p01 = __hfma2(v01, p01, D2);  p23 = __hfma2(v23, p23, D2);
                p01 = __hfma2(v01, p01, D1);  p23 = __hfma2(v23, p23, D1);
                __half2 h01 = __hfma2(v01, p01, y01);
                __half2 h23 = __hfma2(v23, p23, y23);
                hh[j0 * (2 * HPADW) + m0] = __low2half(h01);
                hh[j1 * (2 * HPADW) + m0] = __high2half(h01);
                hh[j0 * (2 * HPADW) + m1] = __low2half(h23);
                hh[j1 * (2 * HPADW) + m1] = __high2half(h23);
            }
        }
        __syncthreads();   // sync#1: h ready, all d reads complete

        // ---- prefetch next pair's d tiles (overlaps GEMM2) ----
        if (p + 1 < TILES_PER_CTA / 2) {
#pragma unroll
            for (int sub = 0; sub < 2; ++sub) {
                uint32_t* dd = sub ? d_sw1 : d_sw0;
                const float* dptr = dists + (size_t)(biA + 2 + sub) * (N_PART * BASIS);
                for (int idx = tid; idx < N_PART * (BASIS / 2); idx += 256) {
                    int j = idx >> 4, q = idx & 15;
                    float2 v = *(const float2*)(dptr + j * BASIS + q * 2);
                    dd[j * DPADW + q] = pack_h2(v.x, v.y);
                }
            }
        }

        // ---- GEMM2 + epi2 for both sub-tiles ----
#pragma unroll
        for (int sub = 0; sub < 2; ++sub) {
            const uint32_t lh = ldsm_h[sub];
            const int bi = biA + sub;
            const int i  = bi & 63;
            float acc[10][4];
#pragma unroll
            for (int nt = 0; nt < 10; ++nt) {
                acc[nt][0] = 0.f; acc[nt][1] = 0.f;
                acc[nt][2] = 0.f; acc[nt][3] = 0.f;
            }
#pragma unroll
            for (int kp = 0; kp < 8; kp += 2) {
#pragma unroll
                for (int nt = 0; nt < 10; ++nt) {
                    uint32_t r0, r1, r2, r3;
                    LDSM4(r0, r1, r2, r3, lh + nt * (8 * HPADW * 4) + kp * 32);
                    mma_f16(acc[nt], a2r[kp],     r0, r1);
                    mma_f16(acc[nt], a2r[kp + 1], r2, r3);
                }
            }
            float o0 = 0.f, o1 = 0.f;
#pragma unroll
            for (int nt = 0; nt < 10; ++nt) {
                const int j0 = nt * 8 + 2 * tg;
                const int j1 = j0 + 1;
                const float w00 = acc[nt][0] + kb2a;
                const float w01 = acc[nt][1] + kb2a;
                const float w10 = acc[nt][2] + kb2b;
                const float w11 = acc[nt][3] + kb2b;
                if (j0 != i) {
                    o0 = fmaf(w00, zs_s[j0 * ZPAD + m0], o0);
                    o1 = fmaf(w10, zs_s[j0 * ZPAD + m1], o1);
                }
                if (j1 != i) {
                    o0 = fmaf(w01, zs_s[j1 * ZPAD + m0], o0);
                    o1 = fmaf(w11, zs_s[j1 * ZPAD + m1], o1);
                }
            }
            o0 += __shfl_xor_sync(0xFFFFFFFFu, o0, 1);
            o0 += __shfl_xor_sync(0xFFFFFFFFu, o0, 2);
            o1 += __shfl_xor_sync(0xFFFFFFFFu, o1, 1);
            o1 += __shfl_xor_sync(0xFFFFFFFFu, o1, 2);
            if (tg == 0) {
                g_zsout[(size_t)bi * KDIM + m0] = o0;
                g_zsout[(size_t)bi * KDIM + m1] = o1;
            }
        }
        __syncthreads();   // sync#2: fills visible, h buffers free
    }
}

// ---------------------------------------------------------------------------
extern "C" void kernel_launch(void* const* d_in, const int* in_sizes, int n_in,
                              void* d_out, int out_size) {
    const float* dists = (const float*)d_in[0];
    const float* emb_e = (const float*)d_in[1];
    const float* emb_n = (const float*)d_in[2];
    const float* kW1   = (const float*)d_in[3];
    const float* kb1   = (const float*)d_in[4];
    const float* kW2   = (const float*)d_in[5];
    const float* kb2   = (const float*)d_in[6];
    const float* eiW   = (const float*)d_in[7];
    const float* eoW1  = (const float*)d_in[8];
    const float* eob1  = (const float*)d_in[9];
    const float* eoW2  = (const float*)d_in[10];
    const float* eob2  = (const float*)d_in[11];
    float* xs = (float*)d_out;

    const int cf_smem = SMEM_WORDS * 4;                    // 98560 B
    const int oz_smem = (4 * 128 * ASTR + 256) * 4;        // 140288 B
    cudaFuncSetAttribute(cfconv_mma_kernel,
                         cudaFuncAttributeMaxDynamicSharedMemorySize, cf_smem);
    cudaFuncSetAttribute(outzs_mma_kernel,
                         cudaFuncAttributeMaxDynamicSharedMemorySize, oz_smem);

    z0_kernel<<<1, 128>>>(emb_e, eiW);
    fill0_kernel<<<(BSZ * N_PART * KDIM + 255) / 256, 256>>>(emb_e, emb_n, xs);

    for (int l = 0; l < LAYERS; ++l) {
        cfconv_mma_kernel<<<CFC_GRID, 256, cf_smem>>>(dists,
                                    kW1 + (size_t)l * BASIS * KDIM,
                                    kb1 + (size_t)l * KDIM,
                                    kW2 + (size_t)l * KDIM * KDIM,
                                    kb2 + (size_t)l * KDIM);
        const float* eiW_next = (l + 1 < LAYERS)
                              ? eiW + (size_t)(l + 1) * DDIM * KDIM : nullptr;
        outzs_mma_kernel<<<NBI / 128, 256, oz_smem>>>(
                                     eoW1 + (size_t)l * KDIM * DDIM,
                                     eob1 + (size_t)l * DDIM,
                                     eoW2 + (size_t)l * DDIM * DDIM,
                                     eob2 + (size_t)l * DDIM,
                                     eiW_next,
                                     xs);
    }
}